// round 14
// baseline (speedup 1.0000x reference)
#include <cuda_runtime.h>
#include <cuda_bf16.h>
#include <cstdint>
#include <math.h>

#define S 64
#define T 64
#define B 64
#define V 32000
#define E 128
#define EH 256
#define DH 256
#define G3 768   // 3*EH == 3*DH

// ------------------------------------------------------------------ scratch
__device__ float g_emb[S * B * E];            // embedded source          2 MB
__device__ float g_gif[S * B * G3];           // fwd input proj (+bih)   12 MB
__device__ float g_gib[S * B * G3];           // bwd input proj (+bih)   12 MB
__device__ float g_henc[2][2][B * EH];        // [dir][buf] enc hidden
__device__ float g_bse[B * S * 2 * EH];       // enc outputs [b][s][512]  8 MB
__device__ float g_encproj[B * S * DH];       // W_e @ enc_bse + b        4 MB
__device__ float g_hdec[2][B * DH];           // decoder hidden (dbl buf)
__device__ float g_xcat[(T - 1) * B * 896];   // [h2|weighted|embd]      14 MB

// bf16 split buffers for the tensor-core fc GEMM (stored as ushort)
__device__ __align__(16) unsigned short g_Wh[(size_t)V * 896];   // 57 MB
__device__ __align__(16) unsigned short g_Wl[(size_t)V * 896];   // 57 MB
__device__ __align__(16) unsigned short g_Ah[4096 * 896];        // 7 MB (padded M)
__device__ __align__(16) unsigned short g_Al[4096 * 896];        // 7 MB

// grid-barrier counters (monotonic across graph replays; 2^32 % nblk == 0 so
// wraparound is harmless — all comparisons are modular-relative)
__device__ unsigned int g_bar_enc;
__device__ unsigned int g_bar_dec;

// ------------------------------------------------------------------ ptx helpers
__device__ __forceinline__ uint32_t smem_u32(const void* p) {
    uint32_t a;
    asm("{ .reg .u64 t; cvta.to.shared.u64 t, %1; cvt.u32.u64 %0, t; }" : "=r"(a) : "l"(p));
    return a;
}
__device__ __forceinline__ void cp16(uint32_t dst, const void* src) {
    asm volatile("cp.async.cg.shared.global [%0], [%1], 16;" :: "r"(dst), "l"(src));
}
__device__ __forceinline__ void cp_commit() { asm volatile("cp.async.commit_group;" ::: "memory"); }
template <int N> __device__ __forceinline__ void cp_wait() {
    asm volatile("cp.async.wait_group %0;" :: "n"(N) : "memory");
}
__device__ __forceinline__ void ldsm4(uint32_t& r0, uint32_t& r1, uint32_t& r2, uint32_t& r3,
                                      uint32_t addr) {
    asm volatile("ldmatrix.sync.aligned.m8n8.x4.shared.b16 {%0,%1,%2,%3}, [%4];"
                 : "=r"(r0), "=r"(r1), "=r"(r2), "=r"(r3) : "r"(addr));
}
// D(4xf32) += A(4xb32 bf16x2) * B(2xb32 bf16x2), m16n8k16 row.col
#define MMA_BF16(d, a, b) \
    asm volatile("mma.sync.aligned.m16n8k16.row.col.f32.bf16.bf16.f32 " \
        "{%0,%1,%2,%3}, {%4,%5,%6,%7}, {%8,%9}, {%0,%1,%2,%3};" \
        : "+f"((d)[0]), "+f"((d)[1]), "+f"((d)[2]), "+f"((d)[3]) \
        : "r"((a)[0]), "r"((a)[1]), "r"((a)[2]), "r"((a)[3]), "r"((b)[0]), "r"((b)[1]))

// all-resident grid barrier: arrive (release via fence) + acquire spin
__device__ __forceinline__ void gridbar(unsigned int* bar, unsigned int nblk) {
    __syncthreads();
    __threadfence();
    if (threadIdx.x == 0) {
        unsigned int ticket = atomicAdd(bar, 1u);
        unsigned int target = (ticket - (ticket % nblk)) + nblk;
        unsigned int cur;
        do {
            asm volatile("ld.global.acquire.gpu.u32 %0, [%1];" : "=r"(cur) : "l"(bar));
        } while ((int)(cur - target) < 0);
    }
    __syncthreads();
}

// ------------------------------------------------------------------ helpers
__device__ __forceinline__ unsigned long long pack2(float x) {
    unsigned long long r;
    asm("mov.b64 %0, {%1, %1};" : "=l"(r) : "r"(__float_as_uint(x)));
    return r;
}
__device__ __forceinline__ void ffma2(unsigned long long& d,
                                      unsigned long long a,
                                      unsigned long long b) {
    asm("fma.rn.f32x2 %0, %1, %2, %0;" : "+l"(d) : "l"(a), "l"(b));
}
__device__ __forceinline__ float2 unpack2(unsigned long long v) {
    float2 r;
    asm("mov.b64 {%0, %1}, %2;" : "=f"(r.x), "=f"(r.y) : "l"(v));
    return r;
}
__device__ __forceinline__ float sigm(float x) { return 1.0f / (1.0f + expf(-x)); }

// ------------------------------------------------------------------ trivial
__global__ void k_zero(float* __restrict__ p, int n) {
    int i = blockIdx.x * 256 + threadIdx.x;
    if (i < n) p[i] = 0.f;
}

__global__ void k_embed(const int* __restrict__ src, const float* __restrict__ emb) {
    int row = blockIdx.x * 2 + (threadIdx.x >> 7);
    int e = threadIdx.x & 127;
    int tok = src[row];
    g_emb[(size_t)row * 128 + e] = __ldg(emb + (size_t)tok * 128 + e);
}

// ------------------------------------------------------------------ bf16 split converters
__global__ void k_split_W(const float* __restrict__ W) {
    size_t i = (size_t)blockIdx.x * 256 + threadIdx.x;   // float4 index, exact
    float4 v = __ldg((const float4*)W + i);
    float xs[4] = {v.x, v.y, v.z, v.w};
    unsigned short hs[4], ls[4];
#pragma unroll
    for (int j = 0; j < 4; j++) {
        __nv_bfloat16 h = __float2bfloat16_rn(xs[j]);
        __nv_bfloat16 l = __float2bfloat16_rn(xs[j] - __bfloat162float(h));
        hs[j] = __bfloat16_as_ushort(h);
        ls[j] = __bfloat16_as_ushort(l);
    }
    ((uint2*)g_Wh)[i] = make_uint2((uint32_t)hs[0] | ((uint32_t)hs[1] << 16),
                                   (uint32_t)hs[2] | ((uint32_t)hs[3] << 16));
    ((uint2*)g_Wl)[i] = make_uint2((uint32_t)ls[0] | ((uint32_t)ls[1] << 16),
                                   (uint32_t)ls[2] | ((uint32_t)ls[3] << 16));
}

__global__ void k_split_A() {
    size_t i = (size_t)blockIdx.x * 256 + threadIdx.x;   // float4 index over 4096x896
    int row = (int)(i / 224);                            // 224 float4 per row
    float4 v = (row < 4032) ? ((const float4*)g_xcat)[i]
                            : make_float4(0.f, 0.f, 0.f, 0.f);
    float xs[4] = {v.x, v.y, v.z, v.w};
    unsigned short hs[4], ls[4];
#pragma unroll
    for (int j = 0; j < 4; j++) {
        __nv_bfloat16 h = __float2bfloat16_rn(xs[j]);
        __nv_bfloat16 l = __float2bfloat16_rn(xs[j] - __bfloat162float(h));
        hs[j] = __bfloat16_as_ushort(h);
        ls[j] = __bfloat16_as_ushort(l);
    }
    ((uint2*)g_Ah)[i] = make_uint2((uint32_t)hs[0] | ((uint32_t)hs[1] << 16),
                                   (uint32_t)hs[2] | ((uint32_t)hs[3] << 16));
    ((uint2*)g_Al)[i] = make_uint2((uint32_t)ls[0] | ((uint32_t)ls[1] << 16),
                                   (uint32_t)ls[2] | ((uint32_t)ls[3] << 16));
}

// ------------------------------------------------------------------ mma.sync fc GEMM
// out[m][n] = sum_k A[m][k]*W[n][k] + fcB[n], bf16 split: Ah*Wh + Ah*Wl + Al*Wh.
// CTA tile 128x128, 8 warps (2M x 4N), warp tile 64x32 (4x4 m16n8k16).
// K chunked at 64 (one 128B SW128 row). smem: 3 stages x 64KB = 192KB.
#define FC_SMEM 196608
#define FC_STAGE_SZ 65536
// stage layout: Ah@0, Al@16K, Wh@32K, Wl@48K, each [128 rows][64 k] bf16, 128B/row, SW128
#define SWZ(x) ((uint32_t)(x) ^ ((((uint32_t)(x) >> 7) & 7) << 4))

__device__ __forceinline__ void fc_loads(int c, uint32_t stage, int m0, int n0, int tid) {
    const int k0 = c * 64;
#pragma unroll
    for (int it = 0; it < 16; it++) {
        int i = tid + it * 256;           // 0..4095
        int tile = i >> 10;               // 0:Ah 1:Al 2:Wh 3:Wl
        int j = i & 1023;
        int r = j >> 3, ch = j & 7;
        const unsigned short* base =
            (tile == 0) ? g_Ah + (size_t)(m0 + r) * 896 :
            (tile == 1) ? g_Al + (size_t)(m0 + r) * 896 :
            (tile == 2) ? g_Wh + (size_t)(n0 + r) * 896 :
                          g_Wl + (size_t)(n0 + r) * 896;
        uint32_t dst = stage + tile * 16384 + SWZ(r * 128 + ch * 16);
        cp16(dst, base + k0 + ch * 8);
    }
    cp_commit();
}

__global__ __launch_bounds__(256, 1)
void k_fc(const float* __restrict__ fcB, float* __restrict__ out /* pre-offset +64*V */)
{
    extern __shared__ __align__(128) char sm[];
    const uint32_t sb = smem_u32(sm);
    const int tid = threadIdx.x;
    const int lane = tid & 31;
    const int warp = tid >> 5;
    const int wm = warp & 1;          // M half (0/1)
    const int wn = warp >> 1;         // N quarter (0..3)
    const int m0 = blockIdx.x * 128;  // M fastest: wave shares W tiles via L2
    const int n0 = blockIdx.y * 128;

    // ldmatrix per-thread addressing constants
    const int mt = lane >> 3;         // which 8x8 matrix this thread addresses
    const int t7 = lane & 7;
    const int arow = (mt & 1) * 8 + t7;       // A: matrices 0/1 rows, 2/3 = +8 cols
    const int acol = (mt >> 1) * 16;          // bytes
    const int brow = (mt >> 1) * 8 + t7;      // B: matrices 0/1 = k cols, 2/3 = +8 rows
    const int bcol = (mt & 1) * 16;           // bytes

    float acc[4][4][4];
#pragma unroll
    for (int i = 0; i < 4; i++)
#pragma unroll
        for (int j = 0; j < 4; j++)
#pragma unroll
            for (int q = 0; q < 4; q++) acc[i][j][q] = 0.f;

    fc_loads(0, sb, m0, n0, tid);
    fc_loads(1, sb + FC_STAGE_SZ, m0, n0, tid);

    for (int c = 0; c < 14; c++) {
        if (c + 2 < 14) {
            fc_loads(c + 2, sb + ((c + 2) % 3) * FC_STAGE_SZ, m0, n0, tid);
            cp_wait<2>();
        } else if (c + 1 < 14) {
            cp_wait<1>();
        } else {
            cp_wait<0>();
        }
        __syncthreads();
        const uint32_t stage = sb + (c % 3) * FC_STAGE_SZ;

#pragma unroll
        for (int ks = 0; ks < 4; ks++) {
            const int kb = ks * 32;           // byte offset of this k16 within the 128B row
            uint32_t ah[4][4], al[4][4], bh[4][2], bl[4][2];
#pragma unroll
            for (int i = 0; i < 4; i++) {
                int rowA = wm * 64 + i * 16 + arow;
                uint32_t off = (uint32_t)(rowA * 128) +
                               (((uint32_t)(kb + acol)) ^ (((uint32_t)rowA & 7) << 4));
                ldsm4(ah[i][0], ah[i][1], ah[i][2], ah[i][3], stage + off);
                ldsm4(al[i][0], al[i][1], al[i][2], al[i][3], stage + 16384 + off);
            }
#pragma unroll
            for (int jj = 0; jj < 2; jj++) {
                int rowB = wn * 32 + jj * 16 + brow;
                uint32_t off = (uint32_t)(rowB * 128) +
                               (((uint32_t)(kb + bcol)) ^ (((uint32_t)rowB & 7) << 4));
                ldsm4(bh[jj * 2][0], bh[jj * 2][1], bh[jj * 2 + 1][0], bh[jj * 2 + 1][1],
                      stage + 32768 + off);
                ldsm4(bl[jj * 2][0], bl[jj * 2][1], bl[jj * 2 + 1][0], bl[jj * 2 + 1][1],
                      stage + 49152 + off);
            }
#pragma unroll
            for (int i = 0; i < 4; i++) {
#pragma unroll
                for (int j = 0; j < 4; j++) {
                    MMA_BF16(acc[i][j], ah[i], bh[j]);
                    MMA_BF16(acc[i][j], ah[i], bl[j]);
                    MMA_BF16(acc[i][j], al[i], bh[j]);
                }
            }
        }
        __syncthreads();
    }

    // epilogue: acc -> out (+bias). c0/c1 = row g, cols 2tg..2tg+1; c2/c3 = row g+8.
    const int g = lane >> 2;
    const int tg = lane & 3;
#pragma unroll
    for (int i = 0; i < 4; i++) {
        int m1 = m0 + wm * 64 + i * 16 + g;
        int m2 = m1 + 8;
#pragma unroll
        for (int j = 0; j < 4; j++) {
            int col = n0 + wn * 32 + j * 8 + tg * 2;
            float b0 = __ldg(fcB + col), b1 = __ldg(fcB + col + 1);
            if (m1 < 4032) {
                float2 v = make_float2(acc[i][j][0] + b0, acc[i][j][1] + b1);
                *(float2*)(out + (size_t)m1 * 32000 + col) = v;
            }
            if (m2 < 4032) {
                float2 v = make_float2(acc[i][j][2] + b0, acc[i][j][3] + b1);
                *(float2*)(out + (size_t)m2 * 32000 + col) = v;
            }
        }
    }
}

// ------------------------------------------------------------------ SGEMM (small GEMMs)
__global__ __launch_bounds__(256)
void k_sgemm(const float* __restrict__ A, int lda,
             const float* __restrict__ Bm, int ldb,
             const float* __restrict__ bias,
             float* __restrict__ C, int ldc,
             int M, int N, int K)
{
    __shared__ float As[2][16][128];
    __shared__ float Bs[2][16][128];
    const int tid = threadIdx.x;
    const int tx = tid & 15;
    const int ty = tid >> 4;
    const int m0 = blockIdx.y * 128;
    const int n0 = blockIdx.x * 128;

    const int r0  = tid >> 2;
    const int kq0 = (tid & 3) * 4;

    unsigned long long acc[8][4];
#pragma unroll
    for (int i = 0; i < 8; i++)
#pragma unroll
        for (int j = 0; j < 4; j++) acc[i][j] = 0ULL;

    float4 aR[2], bR[2];
    const int nt = K >> 4;

#pragma unroll
    for (int i = 0; i < 2; i++) {
        int r = r0 + i * 64;
        int am = m0 + r;
        aR[i] = (am < M) ? *(const float4*)(A + (size_t)am * lda + kq0)
                         : make_float4(0.f, 0.f, 0.f, 0.f);
        bR[i] = *(const float4*)(Bm + (size_t)(n0 + r) * ldb + kq0);
    }
#pragma unroll
    for (int i = 0; i < 2; i++) {
        int r = r0 + i * 64;
        As[0][kq0 + 0][r] = aR[i].x; As[0][kq0 + 1][r] = aR[i].y;
        As[0][kq0 + 2][r] = aR[i].z; As[0][kq0 + 3][r] = aR[i].w;
        Bs[0][kq0 + 0][r] = bR[i].x; Bs[0][kq0 + 1][r] = bR[i].y;
        Bs[0][kq0 + 2][r] = bR[i].z; Bs[0][kq0 + 3][r] = bR[i].w;
    }
    __syncthreads();

    for (int t = 0; t < nt; t++) {
        if (t + 1 < nt) {
            int kt = (t + 1) << 4;
#pragma unroll
            for (int i = 0; i < 2; i++) {
                int r = r0 + i * 64;
                int am = m0 + r;
                aR[i] = (am < M) ? *(const float4*)(A + (size_t)am * lda + kt + kq0)
                                 : make_float4(0.f, 0.f, 0.f, 0.f);
                bR[i] = *(const float4*)(Bm + (size_t)(n0 + r) * ldb + kt + kq0);
            }
        }
        const int buf = t & 1;
#pragma unroll
        for (int k = 0; k < 16; k++) {
            float4 a0 = *(const float4*)&As[buf][k][ty * 8];
            float4 a1 = *(const float4*)&As[buf][k][ty * 8 + 4];
            const unsigned long long* bp =
                (const unsigned long long*)&Bs[buf][k][tx * 8];
            unsigned long long b0 = bp[0], b1 = bp[1], b2 = bp[2], b3 = bp[3];
            float av[8] = {a0.x, a0.y, a0.z, a0.w, a1.x, a1.y, a1.z, a1.w};
#pragma unroll
            for (int i = 0; i < 8; i++) {
                unsigned long long aa = pack2(av[i]);
                ffma2(acc[i][0], aa, b0);
                ffma2(acc[i][1], aa, b1);
                ffma2(acc[i][2], aa, b2);
                ffma2(acc[i][3], aa, b3);
            }
        }
        if (t + 1 < nt) {
            const int nb = (t + 1) & 1;
#pragma unroll
            for (int i = 0; i < 2; i++) {
                int r = r0 + i * 64;
                As[nb][kq0 + 0][r] = aR[i].x; As[nb][kq0 + 1][r] = aR[i].y;
                As[nb][kq0 + 2][r] = aR[i].z; As[nb][kq0 + 3][r] = aR[i].w;
                Bs[nb][kq0 + 0][r] = bR[i].x; Bs[nb][kq0 + 1][r] = bR[i].y;
                Bs[nb][kq0 + 2][r] = bR[i].z; Bs[nb][kq0 + 3][r] = bR[i].w;
            }
        }
        __syncthreads();
    }

#pragma unroll
    for (int i = 0; i < 8; i++) {
        int m = m0 + ty * 8 + i;
        if (m < M) {
            float* crow = C + (size_t)m * ldc + n0 + tx * 8;
            const float* brow = bias + n0 + tx * 8;
#pragma unroll
            for (int j = 0; j < 4; j++) {
                float2 v = unpack2(acc[i][j]);
                v.x += brow[j * 2];
                v.y += brow[j * 2 + 1];
                *(float2*)(crow + j * 2) = v;
            }
        }
    }
}

// ------------------------------------------------------------------ persistent encoder scan
// 128 blocks: block = (dir, 4 hidden units). Whh slice lives in smem for all
// 64 steps; hand-rolled grid barrier between steps. g_henc reads use __ldcg
// (L2) because the double-buffered addresses are re-read across steps and L1
// is not coherent across SMs.
__global__ __launch_bounds__(256)
void k_enc_scan(const float* __restrict__ WhhF, const float* __restrict__ WhhB,
                const float* __restrict__ bhhF, const float* __restrict__ bhhB)
{
    __shared__ float ws[12][256];
    const int bid = blockIdx.x;          // 0..127
    const int dir = bid >> 6;
    const int u0 = (bid & 63) * 4;
    const float* Whh = dir ? WhhB : WhhF;
    const float* bhh = dir ? bhhB : bhhF;
    const float* gib = dir ? g_gib : g_gif;

    for (int i = threadIdx.x; i < 12 * 64; i += 256) {
        int j = i >> 6, k4 = i & 63;
        int row = ((j >> 2) << 8) + u0 + (j & 3);
        ((float4*)ws[j])[k4] = __ldg((const float4*)(Whh + (size_t)row * 256) + k4);
    }
    // zero both h buffers (65536 floats / 128 blocks = 512 = 256 float2)
    ((float2*)&g_henc[0][0][0])[bid * 256 + threadIdx.x] = make_float2(0.f, 0.f);
    gridbar(&g_bar_enc, 128);

    const int b = threadIdx.x & 63;
    const int u = threadIdx.x >> 6;
    const int un = u0 + u;
    const float bhr = bhh[un], bhz = bhh[256 + un], bhn = bhh[512 + un];

    for (int s = 0; s < 64; s++) {
        const int spos = dir ? (63 - s) : s;
        const float* hp = &g_henc[dir][s & 1][b * 256];
        float ar = 0.f, az = 0.f, an = 0.f;
#pragma unroll 8
        for (int k4 = 0; k4 < 64; k4++) {
            float4 h4 = __ldcg((const float4*)hp + k4);
            float4 wr = ((const float4*)ws[u])[k4];
            float4 wz = ((const float4*)ws[4 + u])[k4];
            float4 wn = ((const float4*)ws[8 + u])[k4];
            ar += h4.x * wr.x + h4.y * wr.y + h4.z * wr.z + h4.w * wr.w;
            az += h4.x * wz.x + h4.y * wz.y + h4.z * wz.z + h4.w * wz.w;
            an += h4.x * wn.x + h4.y * wn.y + h4.z * wn.z + h4.w * wn.w;
        }
        const float* gi = gib + ((size_t)spos * B + b) * G3;
        float r = sigm(__ldg(gi + un) + ar + bhr);
        float z = sigm(__ldg(gi + 256 + un) + az + bhz);
        float n = tanhf(__ldg(gi + 512 + un) + r * (an + bhn));
        float hprev = __ldcg(hp + un);
        float h2 = (1.f - z) * n + z * hprev;
        g_henc[dir][(s + 1) & 1][b * 256 + un] = h2;
        g_bse[((size_t)b * S + spos) * 512 + dir * 256 + un] = h2;
        gridbar(&g_bar_enc, 128);
    }
}

// ------------------------------------------------------------------ hidden init
__global__ __launch_bounds__(256)
void k_encfc(const float* __restrict__ W, const float* __restrict__ bias)
{
    __shared__ float hc[512];
    const int b = blockIdx.x, n = threadIdx.x;
    hc[n]       = g_henc[0][0][b * 256 + n];
    hc[256 + n] = g_henc[1][0][b * 256 + n];
    __syncthreads();
    float acc = 0.f;
    const float4* wr = (const float4*)(W + (size_t)n * 512);
#pragma unroll 8
    for (int k4 = 0; k4 < 128; k4++) {
        float4 w = __ldg(wr + k4);
        float4 h = ((const float4*)hc)[k4];
        acc += w.x * h.x + w.y * h.y + w.z * h.z + w.w * h.w;
    }
    g_hdec[0][b * 256 + n] = tanhf(acc + bias[n]);
}

// ------------------------------------------------------------------ persistent decoder scan
// 64 blocks. Per step: attention phase (block = batch bid) -> barrier ->
// GRU phase (block = unit group bid, weights resident in smem) -> barrier.
__global__ __launch_bounds__(256)
void k_dec_scan(const float* __restrict__ attnW, const float* __restrict__ attnV,
                const int* __restrict__ trg, const float* __restrict__ decEmb,
                const float* __restrict__ Wih, const float* __restrict__ Whh,
                const float* __restrict__ bih, const float* __restrict__ bhh)
{
    __shared__ float wi[12][640];     // 30 KB
    __shared__ float wh[12][256];     // 12 KB
    __shared__ float hsm[256], q[256], vsm[256], sc[64];

    const int bid = blockIdx.x;       // batch for attn; unit group for GRU
    const int tid = threadIdx.x;
    const int u0 = bid * 4;

    // GRU weight slices: loaded ONCE for all 63 steps
    for (int i = tid; i < 12 * 160; i += 256) {
        int j = i / 160, c = i % 160;
        int row = ((j >> 2) << 8) + u0 + (j & 3);
        ((float4*)wi[j])[c] = __ldg((const float4*)(Wih + (size_t)row * 640) + c);
    }
    for (int i = tid; i < 12 * 64; i += 256) {
        int j = i >> 6, c = i & 63;
        int row = ((j >> 2) << 8) + u0 + (j & 3);
        ((float4*)wh[j])[c] = __ldg((const float4*)(Whh + (size_t)row * 256) + c);
    }
    vsm[tid] = attnV[tid];
    __syncthreads();

    const int gb = tid & 63;          // GRU batch
    const int gu = tid >> 6;          // GRU unit within group
    const int un = u0 + gu;
    const float bir = bih[un] + bhh[un];
    const float biz = bih[256 + un] + bhh[256 + un];
    const float bin = bih[512 + un];
    const float bhn = bhh[512 + un];

    for (int t = 0; t < 63; t++) {
        // ---------------- attention (batch = bid) ----------------
        hsm[tid] = __ldcg(&g_hdec[t & 1][bid * 256 + tid]);
        __syncthreads();
        {
            float acc = 0.f;
            const float4* wr = (const float4*)(attnW + (size_t)tid * 768);
#pragma unroll 8
            for (int k4 = 0; k4 < 64; k4++) {
                float4 w = __ldg(wr + k4);
                float4 hh = ((const float4*)hsm)[k4];
                acc += w.x * hh.x + w.y * hh.y + w.z * hh.z + w.w * hh.w;
            }
            q[tid] = acc;
        }
        __syncthreads();

        const int warp = tid >> 5, lane = tid & 31;
        for (int s = warp; s < 64; s += 8) {
            const float* ep = g_encproj + ((size_t)bid * 64 + s) * 256;
            float sacc = 0.f;
#pragma unroll
            for (int n = lane; n < 256; n += 32)
                sacc += vsm[n] * tanhf(__ldg(ep + n) + q[n]);
#pragma unroll
            for (int off = 16; off; off >>= 1)
                sacc += __shfl_xor_sync(0xffffffffu, sacc, off);
            if (lane == 0) sc[s] = sacc;
        }
        __syncthreads();

        if (warp == 0) {
            float v0 = sc[lane], v1 = sc[lane + 32];
            float m = fmaxf(v0, v1);
#pragma unroll
            for (int off = 16; off; off >>= 1)
                m = fmaxf(m, __shfl_xor_sync(0xffffffffu, m, off));
            float e0 = expf(v0 - m), e1 = expf(v1 - m);
            float ssum = e0 + e1;
#pragma unroll
            for (int off = 16; off; off >>= 1)
                ssum += __shfl_xor_sync(0xffffffffu, ssum, off);
            float inv = 1.f / ssum;
            sc[lane] = e0 * inv;
            sc[lane + 32] = e1 * inv;
        }
        __syncthreads();

        {
            float w0 = 0.f, w1 = 0.f;
            const float* bse = g_bse + (size_t)bid * S * 512;
#pragma unroll 4
            for (int s = 0; s < 64; s++) {
                float a = sc[s];
                w0 += a * __ldg(bse + s * 512 + tid);
                w1 += a * __ldg(bse + s * 512 + 256 + tid);
            }
            float* xrow = g_xcat + ((size_t)t * B + bid) * 896;
            xrow[256 + tid] = w0;
            xrow[512 + tid] = w1;
            if (tid < 128) {
                int tok = trg[t * B + bid];
                xrow[768 + tid] = __ldg(decEmb + (size_t)tok * 128 + tid);
            }
        }
        gridbar(&g_bar_dec, 64);

        // ---------------- GRU (units u0..u0+3, all batches) ----------------
        {
            const float* xrow = g_xcat + ((size_t)t * B + gb) * 896;
            const float* hp = &g_hdec[t & 1][gb * 256];
            float ar = 0.f, az = 0.f, ani = 0.f, anh = 0.f;
#pragma unroll 8
            for (int k4 = 0; k4 < 32; k4++) {       // embd part
                float4 x4 = __ldcg((const float4*)(xrow + 768) + k4);
                float4 wr = ((const float4*)wi[gu])[k4];
                float4 wz = ((const float4*)wi[4 + gu])[k4];
                float4 wn = ((const float4*)wi[8 + gu])[k4];
                ar  += x4.x * wr.x + x4.y * wr.y + x4.z * wr.z + x4.w * wr.w;
                az  += x4.x * wz.x + x4.y * wz.y + x4.z * wz.z + x4.w * wz.w;
                ani += x4.x * wn.x + x4.y * wn.y + x4.z * wn.z + x4.w * wn.w;
            }
#pragma unroll 8
            for (int k4 = 32; k4 < 160; k4++) {     // weighted part
                float4 x4 = __ldcg((const float4*)(xrow + 128) + k4);
                float4 wr = ((const float4*)wi[gu])[k4];
                float4 wz = ((const float4*)wi[4 + gu])[k4];
                float4 wn = ((const float4*)wi[8 + gu])[k4];
                ar  += x4.x * wr.x + x4.y * wr.y + x4.z * wr.z + x4.w * wr.w;
                az  += x4.x * wz.x + x4.y * wz.y + x4.z * wz.z + x4.w * wz.w;
                ani += x4.x * wn.x + x4.y * wn.y + x4.z * wn.z + x4.w * wn.w;
            }
#pragma unroll 8
            for (int k4 = 0; k4 < 64; k4++) {       // h part
                float4 h4 = __ldcg((const float4*)hp + k4);
                float4 wr = ((const float4*)wh[gu])[k4];
                float4 wz = ((const float4*)wh[4 + gu])[k4];
                float4 wn = ((const float4*)wh[8 + gu])[k4];
                ar  += h4.x * wr.x + h4.y * wr.y + h4.z * wr.z + h4.w * wr.w;
                az  += h4.x * wz.x + h4.y * wz.y + h4.z * wz.z + h4.w * wz.w;
                anh += h4.x * wn.x + h4.y * wn.y + h4.z * wn.z + h4.w * wn.w;
            }
            float r = sigm(ar + bir);
            float z = sigm(az + biz);
            float n = tanhf(ani + bin + r * (anh + bhn));
            float hprev = __ldcg(hp + un);
            float h2 = (1.f - z) * n + z * hprev;
            g_hdec[(t + 1) & 1][gb * 256 + un] = h2;
            g_xcat[((size_t)t * B + gb) * 896 + un] = h2;
        }
        gridbar(&g_bar_dec, 64);
    }
}

// ------------------------------------------------------------------ launch
extern "C" void kernel_launch(void* const* d_in, const int* in_sizes, int n_in,
                              void* d_out, int out_size)
{
    (void)in_sizes; (void)n_in; (void)out_size;
    const int*   src     = (const int*)  d_in[0];
    const int*   trg     = (const int*)  d_in[1];
    const float* enc_emb = (const float*)d_in[2];
    const float* eWihF   = (const float*)d_in[3];
    const float* eWhhF   = (const float*)d_in[4];
    const float* ebihF   = (const float*)d_in[5];
    const float* ebhhF   = (const float*)d_in[6];
    const float* eWihB   = (const float*)d_in[7];
    const float* eWhhB   = (const float*)d_in[8];
    const float* ebihB   = (const float*)d_in[9];
    const float* ebhhB   = (const float*)d_in[10];
    const float* efcW    = (const float*)d_in[11];
    const float* efcB    = (const float*)d_in[12];
    const float* attnW   = (const float*)d_in[13];
    const float* attnB   = (const float*)d_in[14];
    const float* attnV   = (const float*)d_in[15];
    const float* dec_emb = (const float*)d_in[16];
    const float* dWih    = (const float*)d_in[17];
    const float* dWhh    = (const float*)d_in[18];
    const float* dbih    = (const float*)d_in[19];
    const float* dbhh    = (const float*)d_in[20];
    const float* fcW     = (const float*)d_in[21];
    const float* fcB     = (const float*)d_in[22];
    float* out = (float*)d_out;

    cudaFuncSetAttribute(k_fc, cudaFuncAttributeMaxDynamicSharedMemorySize, FC_SMEM);

    float *pEmb, *pGif, *pGib, *pBse, *pEncp;
    cudaGetSymbolAddress((void**)&pEmb,  g_emb);
    cudaGetSymbolAddress((void**)&pGif,  g_gif);
    cudaGetSymbolAddress((void**)&pGib,  g_gib);
    cudaGetSymbolAddress((void**)&pBse,  g_bse);
    cudaGetSymbolAddress((void**)&pEncp, g_encproj);

    // 0) split fc_W into bf16 hi/lo (independent of everything else)
    k_split_W<<<28000, 256>>>(fcW);
    // 1) embed source
    k_embed<<<2048, 256>>>(src, enc_emb);
    // 2) hoisted encoder input projections
    k_sgemm<<<dim3(6, 32), 256>>>(pEmb, 128, eWihF, 128, ebihF, pGif, 768, 4096, 768, 128);
    k_sgemm<<<dim3(6, 32), 256>>>(pEmb, 128, eWihB, 128, ebihB, pGib, 768, 4096, 768, 128);
    // 3) encoder scan: ONE persistent kernel (grid barrier per step)
    k_enc_scan<<<128, 256>>>(eWhhF, eWhhB, ebhhF, ebhhB);
    // 4) decoder hidden init + encoder-side attention projection
    k_encfc<<<64, 256>>>(efcW, efcB);
    k_sgemm<<<dim3(2, 32), 256>>>(pBse, 512, attnW + 256, 768, attnB, pEncp, 256, 4096, 256, 512);
    // 5) out[0] = 0
    k_zero<<<(64 * 32000 + 255) / 256, 256>>>(out, 64 * 32000);
    // 6) decoder: ONE persistent kernel (attn + GRU fused, weights resident)
    k_dec_scan<<<64, 256>>>(attnW, attnV, trg, dec_emb, dWih, dWhh, dbih, dbhh);
    // 7) split xcat into bf16 hi/lo (with zero-padding to 4096 rows)
    k_split_A<<<3584, 256>>>();
    // 8) tensor-core fc: out[64:] = xcat @ fc_W^T + fc_b
    k_fc<<<dim3(32, 250), 256, FC_SMEM>>>(fcB, out + (size_t)64 * 32000);
}

// round 16
// speedup vs baseline: 1.0501x; 1.0501x over previous
#include <cuda_runtime.h>
#include <cuda_bf16.h>
#include <cstdint>
#include <math.h>

#define S 64
#define T 64
#define B 64
#define V 32000
#define E 128
#define EH 256
#define DH 256
#define G3 768   // 3*EH == 3*DH

// ------------------------------------------------------------------ scratch
__device__ float g_emb[S * B * E];            // embedded source          2 MB
__device__ float g_gif[S * B * G3];           // fwd input proj (+bih)   12 MB
__device__ float g_gib[S * B * G3];           // bwd input proj (+bih)   12 MB
__device__ float g_henc[2][2][B * EH];        // [dir][buf] enc hidden
__device__ float g_bse[B * S * 2 * EH];       // enc outputs [b][s][512]  8 MB
__device__ float g_encproj[B * S * DH];       // W_e @ enc_bse + b        4 MB
__device__ float g_hdec[2][B * DH];           // decoder hidden (dbl buf)
__device__ float g_xcat[(T - 1) * B * 896];   // [h2|weighted|embd]      14 MB
__device__ float g_part[B * 64 * 4];          // attention partial scores

// bf16 split buffers for the tensor-core fc GEMM (stored as ushort)
__device__ __align__(16) unsigned short g_Wh[(size_t)V * 896];   // 57 MB
__device__ __align__(16) unsigned short g_Wl[(size_t)V * 896];   // 57 MB
__device__ __align__(16) unsigned short g_Ah[4096 * 896];        // 7 MB (padded M)
__device__ __align__(16) unsigned short g_Al[4096 * 896];        // 7 MB

// ------------------------------------------------------------------ ptx helpers
__device__ __forceinline__ uint32_t smem_u32(const void* p) {
    uint32_t a;
    asm("{ .reg .u64 t; cvta.to.shared.u64 t, %1; cvt.u32.u64 %0, t; }" : "=r"(a) : "l"(p));
    return a;
}
__device__ __forceinline__ void cp16(uint32_t dst, const void* src) {
    asm volatile("cp.async.cg.shared.global [%0], [%1], 16;" :: "r"(dst), "l"(src));
}
__device__ __forceinline__ void cp_commit() { asm volatile("cp.async.commit_group;" ::: "memory"); }
template <int N> __device__ __forceinline__ void cp_wait() {
    asm volatile("cp.async.wait_group %0;" :: "n"(N) : "memory");
}
__device__ __forceinline__ void ldsm4(uint32_t& r0, uint32_t& r1, uint32_t& r2, uint32_t& r3,
                                      uint32_t addr) {
    asm volatile("ldmatrix.sync.aligned.m8n8.x4.shared.b16 {%0,%1,%2,%3}, [%4];"
                 : "=r"(r0), "=r"(r1), "=r"(r2), "=r"(r3) : "r"(addr));
}
// D(4xf32) += A(4xb32 bf16x2) * B(2xb32 bf16x2), m16n8k16 row.col
#define MMA_BF16(d, a, b) \
    asm volatile("mma.sync.aligned.m16n8k16.row.col.f32.bf16.bf16.f32 " \
        "{%0,%1,%2,%3}, {%4,%5,%6,%7}, {%8,%9}, {%0,%1,%2,%3};" \
        : "+f"((d)[0]), "+f"((d)[1]), "+f"((d)[2]), "+f"((d)[3]) \
        : "r"((a)[0]), "r"((a)[1]), "r"((a)[2]), "r"((a)[3]), "r"((b)[0]), "r"((b)[1]))

// ------------------------------------------------------------------ helpers
__device__ __forceinline__ unsigned long long pack2(float x) {
    unsigned long long r;
    asm("mov.b64 %0, {%1, %1};" : "=l"(r) : "r"(__float_as_uint(x)));
    return r;
}
__device__ __forceinline__ void ffma2(unsigned long long& d,
                                      unsigned long long a,
                                      unsigned long long b) {
    asm("fma.rn.f32x2 %0, %1, %2, %0;" : "+l"(d) : "l"(a), "l"(b));
}
__device__ __forceinline__ float2 unpack2(unsigned long long v) {
    float2 r;
    asm("mov.b64 {%0, %1}, %2;" : "=f"(r.x), "=f"(r.y) : "l"(v));
    return r;
}
__device__ __forceinline__ float sigm(float x) { return 1.0f / (1.0f + expf(-x)); }
__device__ __forceinline__ float tanh_fast(float x) {
    float r; asm("tanh.approx.f32 %0, %1;" : "=f"(r) : "f"(x)); return r;
}

// ------------------------------------------------------------------ trivial
__global__ void k_zero(float* __restrict__ p, int n) {
    int i = blockIdx.x * 256 + threadIdx.x;
    if (i < n) p[i] = 0.f;
}

__global__ void k_zero_henc() {
    int i = blockIdx.x * 256 + threadIdx.x;
    (&g_henc[0][0][0])[i] = 0.f;
}

__global__ void k_embed(const int* __restrict__ src, const float* __restrict__ emb) {
    int row = blockIdx.x * 2 + (threadIdx.x >> 7);
    int e = threadIdx.x & 127;
    int tok = src[row];
    g_emb[(size_t)row * 128 + e] = __ldg(emb + (size_t)tok * 128 + e);
}

// ------------------------------------------------------------------ bf16 split converters
__global__ void k_split_W(const float* __restrict__ W) {
    size_t i = (size_t)blockIdx.x * 256 + threadIdx.x;   // float4 index, exact
    float4 v = __ldg((const float4*)W + i);
    float xs[4] = {v.x, v.y, v.z, v.w};
    unsigned short hs[4], ls[4];
#pragma unroll
    for (int j = 0; j < 4; j++) {
        __nv_bfloat16 h = __float2bfloat16_rn(xs[j]);
        __nv_bfloat16 l = __float2bfloat16_rn(xs[j] - __bfloat162float(h));
        hs[j] = __bfloat16_as_ushort(h);
        ls[j] = __bfloat16_as_ushort(l);
    }
    ((uint2*)g_Wh)[i] = make_uint2((uint32_t)hs[0] | ((uint32_t)hs[1] << 16),
                                   (uint32_t)hs[2] | ((uint32_t)hs[3] << 16));
    ((uint2*)g_Wl)[i] = make_uint2((uint32_t)ls[0] | ((uint32_t)ls[1] << 16),
                                   (uint32_t)ls[2] | ((uint32_t)ls[3] << 16));
}

__global__ void k_split_A() {
    size_t i = (size_t)blockIdx.x * 256 + threadIdx.x;   // float4 index over 4096x896
    int row = (int)(i / 224);                            // 224 float4 per row
    float4 v = (row < 4032) ? ((const float4*)g_xcat)[i]
                            : make_float4(0.f, 0.f, 0.f, 0.f);
    float xs[4] = {v.x, v.y, v.z, v.w};
    unsigned short hs[4], ls[4];
#pragma unroll
    for (int j = 0; j < 4; j++) {
        __nv_bfloat16 h = __float2bfloat16_rn(xs[j]);
        __nv_bfloat16 l = __float2bfloat16_rn(xs[j] - __bfloat162float(h));
        hs[j] = __bfloat16_as_ushort(h);
        ls[j] = __bfloat16_as_ushort(l);
    }
    ((uint2*)g_Ah)[i] = make_uint2((uint32_t)hs[0] | ((uint32_t)hs[1] << 16),
                                   (uint32_t)hs[2] | ((uint32_t)hs[3] << 16));
    ((uint2*)g_Al)[i] = make_uint2((uint32_t)ls[0] | ((uint32_t)ls[1] << 16),
                                   (uint32_t)ls[2] | ((uint32_t)ls[3] << 16));
}

// ------------------------------------------------------------------ mma.sync fc GEMM
// out[m][n] = sum_k A[m][k]*W[n][k] + fcB[n], bf16 split: Ah*Wh + Ah*Wl + Al*Wh.
// CTA tile 128x128, 8 warps (2M x 4N), warp tile 64x32 (4x4 m16n8k16).
// K chunked at 64 (one 128B SW128 row). smem: 2 stages x 64KB = 128KB.
#define FC_SMEM 131072
#define FC_STAGE_SZ 65536
// stage layout: Ah@0, Al@16K, Wh@32K, Wl@48K, each [128 rows][64 k] bf16, 128B/row, SW128
#define SWZ(x) ((uint32_t)(x) ^ ((((uint32_t)(x) >> 7) & 7) << 4))

__device__ __forceinline__ void fc_loads(int c, uint32_t stage, int m0, int n0, int tid) {
    const int k0 = c * 64;
#pragma unroll
    for (int it = 0; it < 16; it++) {
        int i = tid + it * 256;           // 0..4095
        int tile = i >> 10;               // 0:Ah 1:Al 2:Wh 3:Wl
        int j = i & 1023;
        int r = j >> 3, ch = j & 7;
        const unsigned short* base =
            (tile == 0) ? g_Ah + (size_t)(m0 + r) * 896 :
            (tile == 1) ? g_Al + (size_t)(m0 + r) * 896 :
            (tile == 2) ? g_Wh + (size_t)(n0 + r) * 896 :
                          g_Wl + (size_t)(n0 + r) * 896;
        uint32_t dst = stage + tile * 16384 + SWZ(r * 128 + ch * 16);
        cp16(dst, base + k0 + ch * 8);
    }
    cp_commit();
}

__global__ __launch_bounds__(256, 1)
void k_fc(const float* __restrict__ fcB, float* __restrict__ out /* pre-offset +64*V */)
{
    extern __shared__ __align__(128) char sm[];
    const uint32_t sb = smem_u32(sm);
    const int tid = threadIdx.x;
    const int lane = tid & 31;
    const int warp = tid >> 5;
    const int wm = warp & 1;          // M half (0/1)
    const int wn = warp >> 1;         // N quarter (0..3)
    const int m0 = blockIdx.x * 128;  // M fastest: wave shares W tiles via L2
    const int n0 = blockIdx.y * 128;

    // ldmatrix per-thread addressing constants
    const int mt = lane >> 3;         // which 8x8 matrix this thread addresses
    const int t7 = lane & 7;
    const int arow = (mt & 1) * 8 + t7;       // A: matrices 0/1 rows, 2/3 = +8 cols
    const int acol = (mt >> 1) * 16;          // bytes
    const int brow = (mt >> 1) * 8 + t7;      // B: matrices 0/1 = k cols, 2/3 = +8 rows
    const int bcol = (mt & 1) * 16;           // bytes

    float acc[4][4][4];
#pragma unroll
    for (int i = 0; i < 4; i++)
#pragma unroll
        for (int j = 0; j < 4; j++)
#pragma unroll
            for (int q = 0; q < 4; q++) acc[i][j][q] = 0.f;

    fc_loads(0, sb, m0, n0, tid);

    for (int c = 0; c < 14; c++) {
        const int s = c & 1;
        if (c + 1 < 14) {
            fc_loads(c + 1, sb + (s ^ 1) * FC_STAGE_SZ, m0, n0, tid);
            cp_wait<1>();
        } else {
            cp_wait<0>();
        }
        __syncthreads();
        const uint32_t stage = sb + s * FC_STAGE_SZ;

#pragma unroll
        for (int ks = 0; ks < 4; ks++) {
            const int kb = ks * 32;           // byte offset of this k16 within the 128B row
            uint32_t ah[4][4], al[4][4], bh[4][2], bl[4][2];
#pragma unroll
            for (int i = 0; i < 4; i++) {
                int rowA = wm * 64 + i * 16 + arow;
                uint32_t off = (uint32_t)(rowA * 128) +
                               (((uint32_t)(kb + acol)) ^ (((uint32_t)rowA & 7) << 4));
                ldsm4(ah[i][0], ah[i][1], ah[i][2], ah[i][3], stage + off);
                ldsm4(al[i][0], al[i][1], al[i][2], al[i][3], stage + 16384 + off);
            }
#pragma unroll
            for (int jj = 0; jj < 2; jj++) {
                int rowB = wn * 32 + jj * 16 + brow;
                uint32_t off = (uint32_t)(rowB * 128) +
                               (((uint32_t)(kb + bcol)) ^ (((uint32_t)rowB & 7) << 4));
                ldsm4(bh[jj * 2][0], bh[jj * 2][1], bh[jj * 2 + 1][0], bh[jj * 2 + 1][1],
                      stage + 32768 + off);
                ldsm4(bl[jj * 2][0], bl[jj * 2][1], bl[jj * 2 + 1][0], bl[jj * 2 + 1][1],
                      stage + 49152 + off);
            }
#pragma unroll
            for (int i = 0; i < 4; i++) {
#pragma unroll
                for (int j = 0; j < 4; j++) {
                    MMA_BF16(acc[i][j], ah[i], bh[j]);
                    MMA_BF16(acc[i][j], ah[i], bl[j]);
                    MMA_BF16(acc[i][j], al[i], bh[j]);
                }
            }
        }
        __syncthreads();
    }

    // epilogue: acc -> out (+bias). c0/c1 = row g, cols 2tg..2tg+1; c2/c3 = row g+8.
    const int g = lane >> 2;
    const int tg = lane & 3;
#pragma unroll
    for (int i = 0; i < 4; i++) {
        int m1 = m0 + wm * 64 + i * 16 + g;
        int m2 = m1 + 8;
#pragma unroll
        for (int j = 0; j < 4; j++) {
            int col = n0 + wn * 32 + j * 8 + tg * 2;
            float b0 = __ldg(fcB + col), b1 = __ldg(fcB + col + 1);
            if (m1 < 4032) {
                float2 v = make_float2(acc[i][j][0] + b0, acc[i][j][1] + b1);
                *(float2*)(out + (size_t)m1 * 32000 + col) = v;
            }
            if (m2 < 4032) {
                float2 v = make_float2(acc[i][j][2] + b0, acc[i][j][3] + b1);
                *(float2*)(out + (size_t)m2 * 32000 + col) = v;
            }
        }
    }
}

// ------------------------------------------------------------------ SGEMM (small GEMMs)
__global__ __launch_bounds__(256)
void k_sgemm(const float* __restrict__ A, int lda,
             const float* __restrict__ Bm, int ldb,
             const float* __restrict__ bias,
             float* __restrict__ C, int ldc,
             int M, int N, int K)
{
    __shared__ float As[2][16][128];
    __shared__ float Bs[2][16][128];
    const int tid = threadIdx.x;
    const int tx = tid & 15;
    const int ty = tid >> 4;
    const int m0 = blockIdx.y * 128;
    const int n0 = blockIdx.x * 128;

    const int r0  = tid >> 2;
    const int kq0 = (tid & 3) * 4;

    unsigned long long acc[8][4];
#pragma unroll
    for (int i = 0; i < 8; i++)
#pragma unroll
        for (int j = 0; j < 4; j++) acc[i][j] = 0ULL;

    float4 aR[2], bR[2];
    const int nt = K >> 4;

#pragma unroll
    for (int i = 0; i < 2; i++) {
        int r = r0 + i * 64;
        int am = m0 + r;
        aR[i] = (am < M) ? *(const float4*)(A + (size_t)am * lda + kq0)
                         : make_float4(0.f, 0.f, 0.f, 0.f);
        bR[i] = *(const float4*)(Bm + (size_t)(n0 + r) * ldb + kq0);
    }
#pragma unroll
    for (int i = 0; i < 2; i++) {
        int r = r0 + i * 64;
        As[0][kq0 + 0][r] = aR[i].x; As[0][kq0 + 1][r] = aR[i].y;
        As[0][kq0 + 2][r] = aR[i].z; As[0][kq0 + 3][r] = aR[i].w;
        Bs[0][kq0 + 0][r] = bR[i].x; Bs[0][kq0 + 1][r] = bR[i].y;
        Bs[0][kq0 + 2][r] = bR[i].z; Bs[0][kq0 + 3][r] = bR[i].w;
    }
    __syncthreads();

    for (int t = 0; t < nt; t++) {
        if (t + 1 < nt) {
            int kt = (t + 1) << 4;
#pragma unroll
            for (int i = 0; i < 2; i++) {
                int r = r0 + i * 64;
                int am = m0 + r;
                aR[i] = (am < M) ? *(const float4*)(A + (size_t)am * lda + kt + kq0)
                                 : make_float4(0.f, 0.f, 0.f, 0.f);
                bR[i] = *(const float4*)(Bm + (size_t)(n0 + r) * ldb + kt + kq0);
            }
        }
        const int buf = t & 1;
#pragma unroll
        for (int k = 0; k < 16; k++) {
            float4 a0 = *(const float4*)&As[buf][k][ty * 8];
            float4 a1 = *(const float4*)&As[buf][k][ty * 8 + 4];
            const unsigned long long* bp =
                (const unsigned long long*)&Bs[buf][k][tx * 8];
            unsigned long long b0 = bp[0], b1 = bp[1], b2 = bp[2], b3 = bp[3];
            float av[8] = {a0.x, a0.y, a0.z, a0.w, a1.x, a1.y, a1.z, a1.w};
#pragma unroll
            for (int i = 0; i < 8; i++) {
                unsigned long long aa = pack2(av[i]);
                ffma2(acc[i][0], aa, b0);
                ffma2(acc[i][1], aa, b1);
                ffma2(acc[i][2], aa, b2);
                ffma2(acc[i][3], aa, b3);
            }
        }
        if (t + 1 < nt) {
            const int nb = (t + 1) & 1;
#pragma unroll
            for (int i = 0; i < 2; i++) {
                int r = r0 + i * 64;
                As[nb][kq0 + 0][r] = aR[i].x; As[nb][kq0 + 1][r] = aR[i].y;
                As[nb][kq0 + 2][r] = aR[i].z; As[nb][kq0 + 3][r] = aR[i].w;
                Bs[nb][kq0 + 0][r] = bR[i].x; Bs[nb][kq0 + 1][r] = bR[i].y;
                Bs[nb][kq0 + 2][r] = bR[i].z; Bs[nb][kq0 + 3][r] = bR[i].w;
            }
        }
        __syncthreads();
    }

#pragma unroll
    for (int i = 0; i < 8; i++) {
        int m = m0 + ty * 8 + i;
        if (m < M) {
            float* crow = C + (size_t)m * ldc + n0 + tx * 8;
            const float* brow = bias + n0 + tx * 8;
#pragma unroll
            for (int j = 0; j < 4; j++) {
                float2 v = unpack2(acc[i][j]);
                v.x += brow[j * 2];
                v.y += brow[j * 2 + 1];
                *(float2*)(crow + j * 2) = v;
            }
        }
    }
}

// ------------------------------------------------------------------ encoder step
__global__ __launch_bounds__(256)
void k_enc_step(int s,
                const float* __restrict__ WhhF, const float* __restrict__ WhhB,
                const float* __restrict__ bhhF, const float* __restrict__ bhhB)
{
    __shared__ float ws[12][256];
    const int dir = blockIdx.y;
    const int u0 = blockIdx.x * 4;
    const float* Whh = dir ? WhhB : WhhF;
    const float* bhh = dir ? bhhB : bhhF;
    const float* gib = dir ? g_gib : g_gif;
    const int spos = dir ? (S - 1 - s) : s;

    for (int i = threadIdx.x; i < 12 * 64; i += 256) {
        int j = i >> 6, k4 = i & 63;
        int row = ((j >> 2) << 8) + u0 + (j & 3);
        ((float4*)ws[j])[k4] = __ldg((const float4*)(Whh + (size_t)row * 256) + k4);
    }
    __syncthreads();

    const int b = threadIdx.x & 63;
    const int u = threadIdx.x >> 6;
    const float* hp = &g_henc[dir][s & 1][b * 256];
    float ar = 0.f, az = 0.f, an = 0.f;
#pragma unroll 8
    for (int k4 = 0; k4 < 64; k4++) {
        float4 h4 = __ldg((const float4*)hp + k4);
        float4 wr = ((const float4*)ws[u])[k4];
        float4 wz = ((const float4*)ws[4 + u])[k4];
        float4 wn = ((const float4*)ws[8 + u])[k4];
        ar += h4.x * wr.x + h4.y * wr.y + h4.z * wr.z + h4.w * wr.w;
        az += h4.x * wz.x + h4.y * wz.y + h4.z * wz.z + h4.w * wz.w;
        an += h4.x * wn.x + h4.y * wn.y + h4.z * wn.z + h4.w * wn.w;
    }
    const float* gi = gib + ((size_t)spos * B + b) * G3;
    const int un = u0 + u;
    float r = sigm(__ldg(gi + un) + ar + bhh[un]);
    float z = sigm(__ldg(gi + 256 + un) + az + bhh[256 + un]);
    float n = tanhf(__ldg(gi + 512 + un) + r * (an + bhh[512 + un]));
    float hprev = hp[un];
    float h2 = (1.f - z) * n + z * hprev;
    g_henc[dir][(s + 1) & 1][b * 256 + un] = h2;
    g_bse[((size_t)b * S + spos) * 512 + dir * 256 + un] = h2;
}

// ------------------------------------------------------------------ hidden init
__global__ __launch_bounds__(256)
void k_encfc(const float* __restrict__ W, const float* __restrict__ bias)
{
    __shared__ float hc[512];
    const int b = blockIdx.x, n = threadIdx.x;
    hc[n]       = g_henc[0][0][b * 256 + n];
    hc[256 + n] = g_henc[1][0][b * 256 + n];
    __syncthreads();
    float acc = 0.f;
    const float4* wr = (const float4*)(W + (size_t)n * 512);
#pragma unroll 8
    for (int k4 = 0; k4 < 128; k4++) {
        float4 w = __ldg(wr + k4);
        float4 h = ((const float4*)hc)[k4];
        acc += w.x * h.x + w.y * h.y + w.z * h.z + w.w * h.w;
    }
    g_hdec[0][b * 256 + n] = tanhf(acc + bias[n]);
}

// ------------------------------------------------------------------ attention: energy
// grid (64 batches, 4 n-groups). Block (b, ng): computes q for its 64 n rows
// (exact partition, no redundancy), then partial scores over those n for all
// 64 s with single-MUFU tanh.approx. 4K tanh/block spread over 256 blocks.
__global__ __launch_bounds__(256)
void k_energy(int t, const float* __restrict__ attnW, const float* __restrict__ attnV)
{
    __shared__ float hs[256], qs[64], vs[64];
    const int b = blockIdx.x, ng = blockIdx.y, tid = threadIdx.x;
    const int n0 = ng * 64;
    hs[tid] = g_hdec[t & 1][b * 256 + tid];
    if (tid < 64) vs[tid] = attnV[n0 + tid];
    __syncthreads();

    {   // q[n0+np] = dot(W_h[n0+np, :256], h); 4 lanes per np, shfl-combined
        const int np = tid >> 2, kq = tid & 3;
        float acc = 0.f;
        const float4* wr = (const float4*)(attnW + (size_t)(n0 + np) * 768 + kq * 64);
        const float4* hq = (const float4*)hs + kq * 16;
#pragma unroll
        for (int i = 0; i < 16; i++) {
            float4 w = __ldg(wr + i);
            float4 h = hq[i];
            acc += w.x * h.x + w.y * h.y + w.z * h.z + w.w * h.w;
        }
        acc += __shfl_xor_sync(0xffffffffu, acc, 1);
        acc += __shfl_xor_sync(0xffffffffu, acc, 2);
        if (kq == 0) qs[np] = acc;
    }
    __syncthreads();

    {   // partial score: s = tid>>2, this block's n-range, 16 n per lane
        const int s = tid >> 2, kq = tid & 3;
        const float* ep = g_encproj + ((size_t)b * 64 + s) * 256 + n0 + kq * 16;
        float sacc = 0.f;
#pragma unroll
        for (int i = 0; i < 16; i++)
            sacc += vs[kq * 16 + i] * tanh_fast(__ldg(ep + i) + qs[kq * 16 + i]);
        sacc += __shfl_xor_sync(0xffffffffu, sacc, 1);
        sacc += __shfl_xor_sync(0xffffffffu, sacc, 2);
        if (kq == 0) g_part[((size_t)b * 64 + s) * 4 + ng] = sacc;
    }
}

// ------------------------------------------------------------------ attention: context
// 64 blocks (batch). Sums partials -> softmax -> weighted context + embd gather.
__global__ __launch_bounds__(256)
void k_ctx(int t, const int* __restrict__ trg, const float* __restrict__ decEmb)
{
    __shared__ float sc[64];
    const int b = blockIdx.x, tid = threadIdx.x;
    if (tid < 64) {
        const float* p = g_part + ((size_t)b * 64 + tid) * 4;
        sc[tid] = p[0] + p[1] + p[2] + p[3];
    }
    __syncthreads();

    const int warp = tid >> 5, lane = tid & 31;
    if (warp == 0) {
        float v0 = sc[lane], v1 = sc[lane + 32];
        float m = fmaxf(v0, v1);
#pragma unroll
        for (int off = 16; off; off >>= 1)
            m = fmaxf(m, __shfl_xor_sync(0xffffffffu, m, off));
        float e0 = expf(v0 - m), e1 = expf(v1 - m);
        float ssum = e0 + e1;
#pragma unroll
        for (int off = 16; off; off >>= 1)
            ssum += __shfl_xor_sync(0xffffffffu, ssum, off);
        float inv = 1.f / ssum;
        sc[lane] = e0 * inv;
        sc[lane + 32] = e1 * inv;
    }
    __syncthreads();

    float w0 = 0.f, w1 = 0.f;
    const float* bse = g_bse + (size_t)b * S * 512;
#pragma unroll 4
    for (int s = 0; s < 64; s++) {
        float a = sc[s];
        w0 += a * __ldg(bse + s * 512 + tid);
        w1 += a * __ldg(bse + s * 512 + 256 + tid);
    }
    float* xrow = g_xcat + ((size_t)t * B + b) * 896;
    xrow[256 + tid] = w0;
    xrow[512 + tid] = w1;
    if (tid < 128) {
        int tok = trg[t * B + b];
        xrow[768 + tid] = __ldg(decEmb + (size_t)tok * 128 + tid);
    }
}

// ------------------------------------------------------------------ decoder GRU
__global__ __launch_bounds__(256)
void k_dec_gru(int t,
               const float* __restrict__ Wih, const float* __restrict__ Whh,
               const float* __restrict__ bih, const float* __restrict__ bhh)
{
    __shared__ float wi[12][640];
    __shared__ float wh[12][256];
    const int u0 = blockIdx.x * 4;
    for (int i = threadIdx.x; i < 12 * 160; i += 256) {
        int j = i / 160, c = i % 160;
        int row = ((j >> 2) << 8) + u0 + (j & 3);
        ((float4*)wi[j])[c] = __ldg((const float4*)(Wih + (size_t)row * 640) + c);
    }
    for (int i = threadIdx.x; i < 12 * 64; i += 256) {
        int j = i >> 6, c = i & 63;
        int row = ((j >> 2) << 8) + u0 + (j & 3);
        ((float4*)wh[j])[c] = __ldg((const float4*)(Whh + (size_t)row * 256) + c);
    }
    __syncthreads();

    const int b = threadIdx.x & 63;
    const int u = threadIdx.x >> 6;
    const float* xrow = g_xcat + ((size_t)t * B + b) * 896;
    const float* hp = &g_hdec[t & 1][b * 256];

    float ar = 0.f, az = 0.f, ani = 0.f, anh = 0.f;
#pragma unroll 8
    for (int k4 = 0; k4 < 32; k4++) {
        float4 x4 = __ldg((const float4*)(xrow + 768) + k4);
        float4 wr = ((const float4*)wi[u])[k4];
        float4 wz = ((const float4*)wi[4 + u])[k4];
        float4 wn = ((const float4*)wi[8 + u])[k4];
        ar  += x4.x * wr.x + x4.y * wr.y + x4.z * wr.z + x4.w * wr.w;
        az  += x4.x * wz.x + x4.y * wz.y + x4.z * wz.z + x4.w * wz.w;
        ani += x4.x * wn.x + x4.y * wn.y + x4.z * wn.z + x4.w * wn.w;
    }
#pragma unroll 8
    for (int k4 = 32; k4 < 160; k4++) {
        float4 x4 = __ldg((const float4*)(xrow + 128) + k4);
        float4 wr = ((const float4*)wi[u])[k4];
        float4 wz = ((const float4*)wi[4 + u])[k4];
        float4 wn = ((const float4*)wi[8 + u])[k4];
        ar  += x4.x * wr.x + x4.y * wr.y + x4.z * wr.z + x4.w * wr.w;
        az  += x4.x * wz.x + x4.y * wz.y + x4.z * wz.z + x4.w * wz.w;
        ani += x4.x * wn.x + x4.y * wn.y + x4.z * wn.z + x4.w * wn.w;
    }
#pragma unroll 8
    for (int k4 = 0; k4 < 64; k4++) {
        float4 h4 = __ldg((const float4*)hp + k4);
        float4 wr = ((const float4*)wh[u])[k4];
        float4 wz = ((const float4*)wh[4 + u])[k4];
        float4 wn = ((const float4*)wh[8 + u])[k4];
        ar  += h4.x * wr.x + h4.y * wr.y + h4.z * wr.z + h4.w * wr.w;
        az  += h4.x * wz.x + h4.y * wz.y + h4.z * wz.z + h4.w * wz.w;
        anh += h4.x * wn.x + h4.y * wn.y + h4.z * wn.z + h4.w * wn.w;
    }
    const int un = u0 + u;
    float r = sigm(ar + bih[un] + bhh[un]);
    float z = sigm(az + bih[256 + un] + bhh[256 + un]);
    float n = tanhf(ani + bih[512 + un] + r * (anh + bhh[512 + un]));
    float hprev = hp[un];
    float h2 = (1.f - z) * n + z * hprev;
    g_hdec[(t + 1) & 1][b * 256 + un] = h2;
    float* xout = g_xcat + ((size_t)t * B + b) * 896;
    xout[un] = h2;
}

// ------------------------------------------------------------------ launch
extern "C" void kernel_launch(void* const* d_in, const int* in_sizes, int n_in,
                              void* d_out, int out_size)
{
    (void)in_sizes; (void)n_in; (void)out_size;
    const int*   src     = (const int*)  d_in[0];
    const int*   trg     = (const int*)  d_in[1];
    const float* enc_emb = (const float*)d_in[2];
    const float* eWihF   = (const float*)d_in[3];
    const float* eWhhF   = (const float*)d_in[4];
    const float* ebihF   = (const float*)d_in[5];
    const float* ebhhF   = (const float*)d_in[6];
    const float* eWihB   = (const float*)d_in[7];
    const float* eWhhB   = (const float*)d_in[8];
    const float* ebihB   = (const float*)d_in[9];
    const float* ebhhB   = (const float*)d_in[10];
    const float* efcW    = (const float*)d_in[11];
    const float* efcB    = (const float*)d_in[12];
    const float* attnW   = (const float*)d_in[13];
    const float* attnB   = (const float*)d_in[14];
    const float* attnV   = (const float*)d_in[15];
    const float* dec_emb = (const float*)d_in[16];
    const float* dWih    = (const float*)d_in[17];
    const float* dWhh    = (const float*)d_in[18];
    const float* dbih    = (const float*)d_in[19];
    const float* dbhh    = (const float*)d_in[20];
    const float* fcW     = (const float*)d_in[21];
    const float* fcB     = (const float*)d_in[22];
    float* out = (float*)d_out;

    cudaFuncSetAttribute(k_fc, cudaFuncAttributeMaxDynamicSharedMemorySize, FC_SMEM);

    float *pEmb, *pGif, *pGib, *pBse, *pEncp;
    cudaGetSymbolAddress((void**)&pEmb,  g_emb);
    cudaGetSymbolAddress((void**)&pGif,  g_gif);
    cudaGetSymbolAddress((void**)&pGib,  g_gib);
    cudaGetSymbolAddress((void**)&pBse,  g_bse);
    cudaGetSymbolAddress((void**)&pEncp, g_encproj);

    // 0) split fc_W into bf16 hi/lo (independent of everything else)
    k_split_W<<<28000, 256>>>(fcW);
    // 1) embed source
    k_embed<<<2048, 256>>>(src, enc_emb);
    // 2) hoisted encoder input projections
    k_sgemm<<<dim3(6, 32), 256>>>(pEmb, 128, eWihF, 128, ebihF, pGif, 768, 4096, 768, 128);
    k_sgemm<<<dim3(6, 32), 256>>>(pEmb, 128, eWihB, 128, ebihB, pGib, 768, 4096, 768, 128);
    // 3) encoder scan
    k_zero_henc<<<256, 256>>>();
    for (int s = 0; s < 64; s++)
        k_enc_step<<<dim3(64, 2), 256>>>(s, eWhhF, eWhhB, ebhhF, ebhhB);
    // 4) decoder hidden init + encoder-side attention projection
    k_encfc<<<64, 256>>>(efcW, efcB);
    k_sgemm<<<dim3(2, 32), 256>>>(pBse, 512, attnW + 256, 768, attnB, pEncp, 256, 4096, 256, 512);
    // 5) out[0] = 0
    k_zero<<<(64 * 32000 + 255) / 256, 256>>>(out, 64 * 32000);
    // 6) decoder loop: energy (256 blocks) -> ctx (64) -> GRU (64)
    for (int t = 0; t < 63; t++) {
        k_energy<<<dim3(64, 4), 256>>>(t, attnW, attnV);
        k_ctx<<<64, 256>>>(t, trg, dec_emb);
        k_dec_gru<<<64, 256>>>(t, dWih, dWhh, dbih, dbhh);
    }
    // 7) split xcat into bf16 hi/lo (with zero-padding to 4096 rows)
    k_split_A<<<3584, 256>>>();
    // 8) tensor-core fc: out[64:] = xcat @ fc_W^T + fc_b
    k_fc<<<dim3(32, 250), 256, FC_SMEM>>>(fcB, out + (size_t)64 * 32000);
}